// round 6
// baseline (speedup 1.0000x reference)
#include <cuda_runtime.h>
#include <math.h>
#include <stdint.h>

#define BATCH   4
#define CH      64
#define NTOK    4096
#define TOKALL  16384
#define ATT_SCALE 0.125f
#define BUF_FLOATS 1048576

__device__ float g_scratch[14 * BUF_FLOATS];
__device__ float g_gap[BATCH * CH];

typedef unsigned long long u64;

__device__ __forceinline__ void ffma2(u64 &d, u64 a, u64 b) {
    asm("fma.rn.f32x2 %0, %1, %2, %0;" : "+l"(d) : "l"(a), "l"(b));
}
__device__ __forceinline__ u64 fmul2(u64 a, u64 b) {
    u64 r; asm("mul.rn.f32x2 %0, %1, %2;" : "=l"(r) : "l"(a), "l"(b)); return r;
}
__device__ __forceinline__ u64 fadd2(u64 a, u64 b) {
    u64 r; asm("add.rn.f32x2 %0, %1, %2;" : "=l"(r) : "l"(a), "l"(b)); return r;
}
__device__ __forceinline__ u64 pack2(float x, float y) {
    u64 r; asm("mov.b64 %0, {%1, %2};" : "=l"(r) : "f"(x), "f"(y)); return r;
}
__device__ __forceinline__ float2 unpack2(u64 u) {
    float2 f; asm("mov.b64 {%0, %1}, %2;" : "=f"(f.x), "=f"(f.y) : "l"(u)); return f;
}
__device__ __forceinline__ float gelu_exact(float x) {
    return 0.5f * x * (1.0f + erff(x * 0.70710678118654752440f));
}

// ---------------------------------------------------------------------------
// avgpool 2x2: x [B,C,128,128] -> xp tokens [B*N, C]
// ---------------------------------------------------------------------------
__global__ void avgpool_kernel(const float* __restrict__ x, float* __restrict__ xp) {
    int b  = blockIdx.x >> 6;
    int hp = blockIdx.x & 63;
    const float* xb = x + (size_t)b * CH * 128 * 128;
    float* xpb = xp + ((size_t)b * NTOK + (size_t)hp * 64) * CH;
    for (int idx = threadIdx.x; idx < 64 * CH; idx += blockDim.x) {
        int c  = idx & 63;
        int wp = idx >> 6;
        const float* p = xb + ((size_t)c * 128 + 2 * hp) * 128 + 2 * wp;
        xpb[(size_t)wp * CH + c] = 0.25f * (p[0] + p[1] + p[128] + p[129]);
    }
}

__global__ void gap_kernel(const float* __restrict__ x, float* __restrict__ gap) {
    int bc = blockIdx.x;
    const float* p = x + (size_t)bc * 16384;
    float s = 0.f;
    for (int i = threadIdx.x; i < 16384; i += 256) s += p[i];
    __shared__ float red[256];
    red[threadIdx.x] = s;
    __syncthreads();
    for (int st = 128; st > 0; st >>= 1) {
        if (threadIdx.x < st) red[threadIdx.x] += red[threadIdx.x + st];
        __syncthreads();
    }
    if (threadIdx.x == 0) gap[bc] = red[0] * (1.0f / 16384.0f);
}

// ---------------------------------------------------------------------------
// Fused q/k/v/xV: q,k,v from gap-gated tokens, xV from plain tokens.
// grid 256 blocks (64 tokens each), 256 threads (4 per token), f32x2 o-packed.
// ---------------------------------------------------------------------------
__global__ void qkvo_kernel(const float* __restrict__ xp, const float* __restrict__ gap,
                            const float* __restrict__ Wq, const float* __restrict__ bq,
                            const float* __restrict__ Wk, const float* __restrict__ bk,
                            const float* __restrict__ Wv, const float* __restrict__ bv,
                            const float* __restrict__ Wo, const float* __restrict__ bo,
                            float* __restrict__ q, float* __restrict__ k,
                            float* __restrict__ v, float* __restrict__ xV) {
    extern __shared__ __align__(16) float sm[];
    float* Wt = sm;               // 4 * 4352
    float* xs = sm + 4 * 4352;    // 4352  plain
    float* xg = xs + 4352;        // 4352  gated
    float* gs = xg + 4352;        // 64
    int tid = threadIdx.x;
    int t0 = blockIdx.x * 64;
    int b  = t0 >> 12;
    const float* Ws[4] = {Wq, Wk, Wv, Wo};
    if (tid < 64) gs[tid] = gap[b * 64 + tid];
#pragma unroll
    for (int m = 0; m < 4; m++) {
        const float* W = Ws[m];
        for (int idx = tid; idx < 4096; idx += 256) {
            int o = idx >> 6, ci = idx & 63;
            Wt[m * 4352 + ci * 68 + o] = W[idx];
        }
    }
    __syncthreads();
    for (int idx = tid; idx < 4096; idx += 256) {
        int tt = idx >> 6, ci = idx & 63;
        float xv = xp[(size_t)(t0 + tt) * 64 + ci];
        xs[tt * 68 + ci] = xv;
        xg[tt * 68 + ci] = xv * gs[ci];
    }
    __syncthreads();
    int t = tid >> 2, qd = tid & 3;
    const float* biases[4] = {bq, bk, bv, bo};
    float* outs[4] = {q, k, v, xV};
#pragma unroll
    for (int m = 0; m < 4; m++) {
        const float* xrow = ((m < 3) ? xg : xs) + t * 68;
        const float* bb = biases[m];
        u64 acc[8];
#pragma unroll
        for (int o2 = 0; o2 < 8; o2++)
            acc[o2] = pack2(bb[qd * 16 + 2 * o2], bb[qd * 16 + 2 * o2 + 1]);
        const float* Wm = Wt + m * 4352;
#pragma unroll 8
        for (int ci = 0; ci < 64; ci++) {
            u64 xx = pack2(xrow[ci], xrow[ci]);
            const ulonglong2* wr = reinterpret_cast<const ulonglong2*>(Wm + ci * 68 + qd * 16);
#pragma unroll
            for (int w = 0; w < 4; w++) {
                ulonglong2 wv = wr[w];
                ffma2(acc[w * 2 + 0], xx, wv.x);
                ffma2(acc[w * 2 + 1], xx, wv.y);
            }
        }
        float4* op = reinterpret_cast<float4*>(outs[m] + (size_t)(t0 + t) * 64 + qd * 16);
#pragma unroll
        for (int w = 0; w < 4; w++) {
            float2 a = unpack2(acc[w * 2]);
            float2 c = unpack2(acc[w * 2 + 1]);
            op[w] = make_float4(a.x, a.y, c.x, c.y);
        }
    }
}

// ---------------------------------------------------------------------------
// Generic 64x64 linear (+optional residual, +optional fused LayerNorm).
// grid 256, block 256 (4 threads/token).
// ---------------------------------------------------------------------------
__global__ void linear2_kernel(const float* __restrict__ in0, const float* __restrict__ W,
                               const float* __restrict__ bias, const float* __restrict__ res,
                               const float* __restrict__ lng, const float* __restrict__ lnb,
                               float* __restrict__ out) {
    __shared__ __align__(16) float Wt[4352];
    __shared__ __align__(16) float xs[4352];
    int tid = threadIdx.x;
    int t0 = blockIdx.x * 64;
    for (int idx = tid; idx < 4096; idx += 256) {
        int o = idx >> 6, ci = idx & 63;
        Wt[ci * 68 + o] = W[idx];
    }
    for (int idx = tid; idx < 4096; idx += 256) {
        int tt = idx >> 6, ci = idx & 63;
        xs[tt * 68 + ci] = in0[(size_t)(t0 + tt) * 64 + ci];
    }
    __syncthreads();
    int t = tid >> 2, qd = tid & 3;
    const float* xrow = xs + t * 68;
    u64 acc[8];
#pragma unroll
    for (int o2 = 0; o2 < 8; o2++)
        acc[o2] = pack2(bias[qd * 16 + 2 * o2], bias[qd * 16 + 2 * o2 + 1]);
#pragma unroll 8
    for (int ci = 0; ci < 64; ci++) {
        u64 xx = pack2(xrow[ci], xrow[ci]);
        const ulonglong2* wr = reinterpret_cast<const ulonglong2*>(Wt + ci * 68 + qd * 16);
#pragma unroll
        for (int w = 0; w < 4; w++) {
            ulonglong2 wv = wr[w];
            ffma2(acc[w * 2 + 0], xx, wv.x);
            ffma2(acc[w * 2 + 1], xx, wv.y);
        }
    }
    if (res) {
        const ulonglong2* rr = reinterpret_cast<const ulonglong2*>(res + (size_t)(t0 + t) * 64 + qd * 16);
#pragma unroll
        for (int w = 0; w < 4; w++) {
            ulonglong2 rv = rr[w];
            acc[w * 2 + 0] = fadd2(acc[w * 2 + 0], rv.x);
            acc[w * 2 + 1] = fadd2(acc[w * 2 + 1], rv.y);
        }
    }
    float val[16];
#pragma unroll
    for (int o2 = 0; o2 < 8; o2++) {
        float2 f = unpack2(acc[o2]);
        val[2 * o2] = f.x; val[2 * o2 + 1] = f.y;
    }
    if (lng) {
        float s = 0.f;
#pragma unroll
        for (int i = 0; i < 16; i++) s += val[i];
        s += __shfl_xor_sync(0xffffffffu, s, 1);
        s += __shfl_xor_sync(0xffffffffu, s, 2);
        float mu = s * (1.0f / 64.0f);
        float ss = 0.f;
#pragma unroll
        for (int i = 0; i < 16; i++) { float d = val[i] - mu; ss += d * d; }
        ss += __shfl_xor_sync(0xffffffffu, ss, 1);
        ss += __shfl_xor_sync(0xffffffffu, ss, 2);
        float rstd = rsqrtf(ss * (1.0f / 64.0f) + 1e-5f);
#pragma unroll
        for (int i = 0; i < 16; i++)
            val[i] = (val[i] - mu) * rstd * lng[qd * 16 + i] + lnb[qd * 16 + i];
    }
    float4* op = reinterpret_cast<float4*>(out + (size_t)(t0 + t) * 64 + qd * 16);
#pragma unroll
    for (int w = 0; w < 4; w++)
        op[w] = make_float4(val[4 * w], val[4 * w + 1], val[4 * w + 2], val[4 * w + 3]);
}

// ---------------------------------------------------------------------------
// Precompute composed strip weights: combT_h[j][o] = sum_i convh[o,i]*sch_pw[i,j]
// (same for v), bias_comb[o] = convh_b[o] + sum_i convh[o,i]*(sch_pwb+scv_pwb)[i]
// ---------------------------------------------------------------------------
__global__ void comb_kernel(const float* __restrict__ convh_w, const float* __restrict__ convh_b,
                            const float* __restrict__ sch_pw, const float* __restrict__ sch_pwb,
                            const float* __restrict__ scv_pw, const float* __restrict__ scv_pwb,
                            float* __restrict__ combT_h, float* __restrict__ combT_v,
                            float* __restrict__ bias_comb) {
    extern __shared__ float s[];
    float* A = s; float* B1 = s + 4096; float* B2 = s + 8192;
    int tid = threadIdx.x;
    for (int idx = tid; idx < 4096; idx += 256) {
        A[idx] = convh_w[idx]; B1[idx] = sch_pw[idx]; B2[idx] = scv_pw[idx];
    }
    __syncthreads();
    for (int e = tid; e < 4096; e += 256) {
        int o = e >> 6, j = e & 63;
        float sh = 0.f, sv = 0.f;
        for (int i = 0; i < 64; i++) {
            float a = A[o * 64 + i];
            sh += a * B1[i * 64 + j];
            sv += a * B2[i * 64 + j];
        }
        combT_h[j * 64 + o] = sh;
        combT_v[j * 64 + o] = sv;
    }
    if (tid < 64) {
        float sb = 0.f;
        for (int i = 0; i < 64; i++) sb += A[tid * 64 + i] * (sch_pwb[i] + scv_pwb[i]);
        bias_comb[tid] = convh_b[tid] + sb;
    }
}

// ---------------------------------------------------------------------------
// Fused strip branch: dw5(vert)+gelu and dw5(horz)+gelu, then composed
// double 64x64 matvec -> prompt_h. grid 256, block 256.
// ---------------------------------------------------------------------------
__global__ void strip_kernel(const float* __restrict__ xp,
                             const float* __restrict__ sch_dw, const float* __restrict__ sch_dwb,
                             const float* __restrict__ scv_dw, const float* __restrict__ scv_dwb,
                             const float* __restrict__ combT_h, const float* __restrict__ combT_v,
                             const float* __restrict__ bias_comb, float* __restrict__ out) {
    extern __shared__ __align__(16) float sm[];
    float* WtH = sm;            // 4352
    float* WtV = sm + 4352;
    float* gh  = sm + 8704;
    float* gv  = sm + 13056;
    int tid = threadIdx.x;
    int t0 = blockIdx.x * 64;
    for (int idx = tid; idx < 4096; idx += 256) {
        int j = idx >> 6, o = idx & 63;
        WtH[j * 68 + o] = combT_h[idx];
        WtV[j * 68 + o] = combT_v[idx];
    }
    for (int idx = tid; idx < 4096; idx += 256) {
        int tt = idx >> 6, ci = idx & 63;
        int token = t0 + tt;
        int h = (token >> 6) & 63, w = token & 63;
        size_t base = (size_t)token * 64 + ci;
        float ah = sch_dwb[ci], av = scv_dwb[ci];
#pragma unroll
        for (int d = -2; d <= 2; d++) {
            int hh = h + d;
            if (hh >= 0 && hh < 64) ah += sch_dw[ci * 5 + d + 2] * xp[base + (ptrdiff_t)d * 4096];
            int ww = w + d;
            if (ww >= 0 && ww < 64) av += scv_dw[ci * 5 + d + 2] * xp[base + (ptrdiff_t)d * 64];
        }
        gh[tt * 68 + ci] = gelu_exact(ah);
        gv[tt * 68 + ci] = gelu_exact(av);
    }
    __syncthreads();
    int t = tid >> 2, qd = tid & 3;
    const float* hrow = gh + t * 68;
    const float* vrow = gv + t * 68;
    u64 acc[8];
#pragma unroll
    for (int o2 = 0; o2 < 8; o2++)
        acc[o2] = pack2(bias_comb[qd * 16 + 2 * o2], bias_comb[qd * 16 + 2 * o2 + 1]);
#pragma unroll 4
    for (int ci = 0; ci < 64; ci++) {
        u64 hx = pack2(hrow[ci], hrow[ci]);
        u64 vx = pack2(vrow[ci], vrow[ci]);
        const ulonglong2* wh = reinterpret_cast<const ulonglong2*>(WtH + ci * 68 + qd * 16);
        const ulonglong2* wv = reinterpret_cast<const ulonglong2*>(WtV + ci * 68 + qd * 16);
#pragma unroll
        for (int w = 0; w < 4; w++) {
            ulonglong2 wh2 = wh[w];
            ulonglong2 wv2 = wv[w];
            ffma2(acc[w * 2 + 0], hx, wh2.x);
            ffma2(acc[w * 2 + 1], hx, wh2.y);
            ffma2(acc[w * 2 + 0], vx, wv2.x);
            ffma2(acc[w * 2 + 1], vx, wv2.y);
        }
    }
    float4* op = reinterpret_cast<float4*>(out + (size_t)(t0 + t) * 64 + qd * 16);
#pragma unroll
    for (int w = 0; w < 4; w++) {
        float2 a = unpack2(acc[w * 2]);
        float2 c = unpack2(acc[w * 2 + 1]);
        op[w] = make_float4(a.x, a.y, c.x, c.y);
    }
}

// ---------------------------------------------------------------------------
// Depthwise 3x3 conv + bias + exact GELU, zero pad 1.
// ---------------------------------------------------------------------------
__global__ void dwconv3x3_kernel(const float* __restrict__ in,
                                 const float* __restrict__ wt,
                                 const float* __restrict__ bias,
                                 float* __restrict__ out) {
    int idx = blockIdx.x * 256 + threadIdx.x;
    int c = idx & 63;
    int g = idx >> 6;
    int n = g & 4095;
    int b = g >> 12;
    int h = n >> 6, w = n & 63;
    float acc = bias[c];
#pragma unroll
    for (int ky = 0; ky < 3; ky++) {
#pragma unroll
        for (int kx = 0; kx < 3; kx++) {
            int hh = h + ky - 1, ww = w + kx - 1;
            if (hh >= 0 && hh < 64 && ww >= 0 && ww < 64) {
                size_t src = (((size_t)b << 12) | ((size_t)hh << 6) | (size_t)ww) * 64 + c;
                acc += wt[c * 9 + ky * 3 + kx] * in[src];
            }
        }
    }
    out[(size_t)g * 64 + c] = gelu_exact(acc);
}

// ---------------------------------------------------------------------------
// Flash attention, fp32 via f32x2 split-K packing.
// grid (64, B), 256 threads (16x16), 4x4 tiles, online softmax.
// smem: Qs[64][64] (pre-scaled) + Ks[64][68] + VsT[64][68] + Ps[64][64]
//     = 16896 floats = 67584 B dynamic.
// Thread (ty,tx): rows i0..i0+3 (i0=4*ty), key/out cols {tx,tx+16,tx+32,tx+48}.
// ---------------------------------------------------------------------------
__global__ void attn_kernel(const float* __restrict__ Q, const float* __restrict__ K,
                            const float* __restrict__ V, float* __restrict__ O) {
    extern __shared__ __align__(16) float sm[];
    float* Qs  = sm;                  // [i][c] pitch 64
    float* Ks  = sm + 4096;           // [j][c] pitch 68
    float* VsT = sm + 4096 + 4352;    // [c][j] pitch 68
    float* Ps  = sm + 4096 + 8704;    // [i][j] pitch 64

    int b  = blockIdx.y;
    int qt = blockIdx.x;
    const float* Qb = Q + ((size_t)b * NTOK + (size_t)qt * 64) * 64;
    const float* Kb = K + (size_t)b * NTOK * 64;
    const float* Vb = V + (size_t)b * NTOK * 64;
    float* Ob = O + ((size_t)b * NTOK + (size_t)qt * 64) * 64;

    int tid = threadIdx.x;
    int tx = tid & 15, ty = tid >> 4;
    int i0 = ty * 4;

    for (int idx = tid; idx < 4096; idx += 256) Qs[idx] = Qb[idx] * ATT_SCALE;

    float m[4], l[4];
    u64 o2[4][4];
#pragma unroll
    for (int ii = 0; ii < 4; ii++) {
        m[ii] = -1e30f; l[ii] = 0.f;
#pragma unroll
        for (int cc = 0; cc < 4; cc++) o2[ii][cc] = 0ull;
    }

    for (int kt = 0; kt < 64; kt++) {
        __syncthreads();
        const float* Kt = Kb + (size_t)kt * 4096;
        const float* Vt = Vb + (size_t)kt * 4096;
        // K tile: [j][c] pitch 68, vectorized
        for (int i4 = tid; i4 < 1024; i4 += 256) {
            int j = i4 >> 4, c = (i4 & 15) * 4;
            float4 kv = *reinterpret_cast<const float4*>(Kt + j * 64 + c);
            *reinterpret_cast<float4*>(&Ks[j * 68 + c]) = kv;
        }
        // V tile transposed: VsT[c][j]
        for (int idx = tid; idx < 4096; idx += 256) {
            int j = idx >> 6, c = idx & 63;
            VsT[c * 68 + j] = Vt[idx];
        }
        __syncthreads();

        // S = Qs @ Ks^T  (split over c pairs in f32x2 lanes)
        u64 s2[4][4];
#pragma unroll
        for (int ii = 0; ii < 4; ii++)
#pragma unroll
            for (int jj = 0; jj < 4; jj++) s2[ii][jj] = 0ull;

#pragma unroll 4
        for (int c4 = 0; c4 < 64; c4 += 4) {
            ulonglong2 av[4], bv[4];
#pragma unroll
            for (int ii = 0; ii < 4; ii++)
                av[ii] = *reinterpret_cast<const ulonglong2*>(Qs + (i0 + ii) * 64 + c4);
#pragma unroll
            for (int jj = 0; jj < 4; jj++)
                bv[jj] = *reinterpret_cast<const ulonglong2*>(Ks + (tx + 16 * jj) * 68 + c4);
#pragma unroll
            for (int ii = 0; ii < 4; ii++)
#pragma unroll
                for (int jj = 0; jj < 4; jj++) {
                    ffma2(s2[ii][jj], av[ii].x, bv[jj].x);
                    ffma2(s2[ii][jj], av[ii].y, bv[jj].y);
                }
        }

        // online softmax
#pragma unroll
        for (int ii = 0; ii < 4; ii++) {
            float s[4];
#pragma unroll
            for (int jj = 0; jj < 4; jj++) {
                float2 f = unpack2(s2[ii][jj]);
                s[jj] = f.x + f.y;
            }
            float rm = fmaxf(fmaxf(s[0], s[1]), fmaxf(s[2], s[3]));
#pragma unroll
            for (int d = 8; d > 0; d >>= 1)
                rm = fmaxf(rm, __shfl_xor_sync(0xffffffffu, rm, d, 16));
            float mn = fmaxf(m[ii], rm);
            float sf = __expf(m[ii] - mn);
            float rs = 0.f;
#pragma unroll
            for (int jj = 0; jj < 4; jj++) {
                s[jj] = __expf(s[jj] - mn);
                rs += s[jj];
            }
#pragma unroll
            for (int d = 8; d > 0; d >>= 1)
                rs += __shfl_xor_sync(0xffffffffu, rs, d, 16);
            l[ii] = l[ii] * sf + rs;
            m[ii] = mn;
            u64 sf2 = pack2(sf, sf);
#pragma unroll
            for (int cc = 0; cc < 4; cc++) o2[ii][cc] = fmul2(o2[ii][cc], sf2);
            Ps[(i0 + ii) * 64 + tx]      = s[0];
            Ps[(i0 + ii) * 64 + tx + 16] = s[1];
            Ps[(i0 + ii) * 64 + tx + 32] = s[2];
            Ps[(i0 + ii) * 64 + tx + 48] = s[3];
        }
        __syncwarp();

        // O += P @ V  (split over j pairs in f32x2 lanes)
#pragma unroll 4
        for (int j4 = 0; j4 < 64; j4 += 4) {
            ulonglong2 av[4], bv[4];
#pragma unroll
            for (int ii = 0; ii < 4; ii++)
                av[ii] = *reinterpret_cast<const ulonglong2*>(Ps + (i0 + ii) * 64 + j4);
#pragma unroll
            for (int cc = 0; cc < 4; cc++)
                bv[cc] = *reinterpret_cast<const ulonglong2*>(VsT + (tx + 16 * cc) * 68 + j4);
#pragma unroll
            for (int ii = 0; ii < 4; ii++)
#pragma unroll
                for (int cc = 0; cc < 4; cc++) {
                    ffma2(o2[ii][cc], av[ii].x, bv[cc].x);
                    ffma2(o2[ii][cc], av[ii].y, bv[cc].y);
                }
        }
    }

#pragma unroll
    for (int ii = 0; ii < 4; ii++) {
        float inv = 1.0f / l[ii];
#pragma unroll
        for (int cc = 0; cc < 4; cc++) {
            float2 f = unpack2(o2[ii][cc]);
            Ob[(i0 + ii) * 64 + tx + 16 * cc] = (f.x + f.y) * inv;
        }
    }
}

// ---------------------------------------------------------------------------
// Bilinear x2 upsample, align_corners=True. tokens [B,N,C] -> [B,C,128,128]
// ---------------------------------------------------------------------------
__global__ void upsample_kernel(const float* __restrict__ in, float* __restrict__ out) {
    int tid = threadIdx.x;
    int c = tid & 63;
    int p = blockIdx.x * 4 + (tid >> 6);
    int b = p >> 14;
    int rem = p & 16383;
    int y = rem >> 7, x = rem & 127;
    float sy = (float)y * (63.0f / 127.0f);
    int y0 = (int)sy; float wy = sy - (float)y0; int y1 = min(y0 + 1, 63);
    float sx = (float)x * (63.0f / 127.0f);
    int x0 = (int)sx; float wx = sx - (float)x0; int x1 = min(x0 + 1, 63);
    const float* base = in + (size_t)b * NTOK * 64;
    float v00 = base[((size_t)y0 * 64 + x0) * 64 + c];
    float v01 = base[((size_t)y0 * 64 + x1) * 64 + c];
    float v10 = base[((size_t)y1 * 64 + x0) * 64 + c];
    float v11 = base[((size_t)y1 * 64 + x1) * 64 + c];
    float r0 = v00 * (1.0f - wx) + v01 * wx;
    float r1 = v10 * (1.0f - wx) + v11 * wx;
    out[(((size_t)b * 64 + c) * 128 + y) * 128 + x] = r0 * (1.0f - wy) + r1 * wy;
}

// ---------------------------------------------------------------------------
extern "C" void kernel_launch(void* const* d_in, const int* in_sizes, int n_in,
                              void* d_out, int out_size) {
    const float* x       = (const float*)d_in[0];
    const float* Wq      = (const float*)d_in[1];
    const float* bq      = (const float*)d_in[2];
    const float* Wk      = (const float*)d_in[3];
    const float* bk      = (const float*)d_in[4];
    const float* Wv      = (const float*)d_in[5];
    const float* bv      = (const float*)d_in[6];
    const float* Wl      = (const float*)d_in[7];
    const float* bl      = (const float*)d_in[8];
    const float* Wo      = (const float*)d_in[9];
    const float* bo      = (const float*)d_in[10];
    const float* Wp      = (const float*)d_in[11];
    const float* bp      = (const float*)d_in[12];
    const float* sch_dw  = (const float*)d_in[13];
    const float* sch_dwb = (const float*)d_in[14];
    const float* sch_pw  = (const float*)d_in[15];
    const float* sch_pwb = (const float*)d_in[16];
    const float* scv_dw  = (const float*)d_in[17];
    const float* scv_dwb = (const float*)d_in[18];
    const float* scv_pw  = (const float*)d_in[19];
    const float* scv_pwb = (const float*)d_in[20];
    const float* convh_w = (const float*)d_in[21];
    const float* convh_b = (const float*)d_in[22];
    const float* dsc_dw  = (const float*)d_in[23];
    const float* dsc_dwb = (const float*)d_in[24];
    const float* dsc_pw  = (const float*)d_in[25];
    const float* dsc_pwb = (const float*)d_in[26];
    const float* ln_g    = (const float*)d_in[27];
    const float* ln_b    = (const float*)d_in[28];
    float* outp = (float*)d_out;

    float* S = nullptr; float* gap = nullptr;
    cudaGetSymbolAddress((void**)&S, g_scratch);
    cudaGetSymbolAddress((void**)&gap, g_gap);

    float* xp    = S + 0  * BUF_FLOATS;
    float* q     = S + 1  * BUF_FLOATS;
    float* k     = S + 2  * BUF_FLOATS;
    float* v     = S + 3  * BUF_FLOATS;
    float* xV    = S + 4  * BUF_FLOATS;
    float* attn1 = S + 5  * BUF_FLOATS;
    float* pl    = S + 6  * BUF_FLOATS;
    float* ph    = S + 7  * BUF_FLOATS;
    float* attn2 = S + 8  * BUF_FLOATS;
    float* pn    = S + 9  * BUF_FLOATS;
    float* tA    = S + 10 * BUF_FLOATS;
    float* dsco  = S + 11 * BUF_FLOATS;
    float* combT_h   = S + 12 * BUF_FLOATS;
    float* combT_v   = combT_h + 4096;
    float* bias_comb = combT_h + 8192;

    static int attr_done = 0;
    if (!attr_done) {
        cudaFuncSetAttribute(attn_kernel, cudaFuncAttributeMaxDynamicSharedMemorySize, 67584);
        cudaFuncSetAttribute(qkvo_kernel, cudaFuncAttributeMaxDynamicSharedMemorySize, 104768);
        cudaFuncSetAttribute(strip_kernel, cudaFuncAttributeMaxDynamicSharedMemorySize, 69632);
        cudaFuncSetAttribute(comb_kernel, cudaFuncAttributeMaxDynamicSharedMemorySize, 49152);
        attr_done = 1;
    }

    // pooled tokens + GAP + composed strip weights
    avgpool_kernel<<<BATCH * 64, 256>>>(x, xp);
    gap_kernel<<<BATCH * CH, 256>>>(x, gap);
    comb_kernel<<<1, 256, 49152>>>(convh_w, convh_b, sch_pw, sch_pwb, scv_pw, scv_pwb,
                                   combT_h, combT_v, bias_comb);

    // q/k/v (gated) + xV (plain)
    qkvo_kernel<<<256, 256, 104768>>>(xp, gap, Wq, bq, Wk, bk, Wv, bv, Wo, bo, q, k, v, xV);

    // self-attention -> prompt_l
    attn_kernel<<<dim3(64, BATCH), 256, 67584>>>(q, k, v, attn1);
    linear2_kernel<<<256, 256>>>(attn1, Wl, bl, nullptr, nullptr, nullptr, pl);

    // high-frequency branch (fused)
    strip_kernel<<<256, 256, 69632>>>(xp, sch_dw, sch_dwb, scv_dw, scv_dwb,
                                      combT_h, combT_v, bias_comb, ph);

    // cross-attention -> prompt, +xV residual, LayerNorm (fused epilogue)
    attn_kernel<<<dim3(64, BATCH), 256, 67584>>>(ph, pl, xV, attn2);
    linear2_kernel<<<256, 256>>>(attn2, Wp, bp, xV, ln_g, ln_b, pn);

    // dsc: dw3x3 -> GELU -> pw + residual
    dwconv3x3_kernel<<<TOKALL * CH / 256, 256>>>(pn, dsc_dw, dsc_dwb, tA);
    linear2_kernel<<<256, 256>>>(tA, dsc_pw, dsc_pwb, pn, nullptr, nullptr, dsco);

    // bilinear x2 upsample
    upsample_kernel<<<BATCH * 128 * 128 / 4, 256>>>(dsco, outp);

    (void)in_sizes; (void)n_in; (void)out_size;
}

// round 8
// speedup vs baseline: 1.8855x; 1.8855x over previous
#include <cuda_runtime.h>
#include <math.h>
#include <stdint.h>

#define BATCH   4
#define CH      64
#define NTOK    4096
#define TOKALL  16384
#define ATT_SCALE 0.125f
#define BUF_FLOATS 1048576

__device__ float g_scratch[14 * BUF_FLOATS];
__device__ float g_gap[BATCH * CH];

typedef unsigned long long u64;

__device__ __forceinline__ void ffma2(u64 &d, u64 a, u64 b) {
    asm("fma.rn.f32x2 %0, %1, %2, %0;" : "+l"(d) : "l"(a), "l"(b));
}
__device__ __forceinline__ u64 fadd2(u64 a, u64 b) {
    u64 r; asm("add.rn.f32x2 %0, %1, %2;" : "=l"(r) : "l"(a), "l"(b)); return r;
}
__device__ __forceinline__ u64 pack2(float x, float y) {
    u64 r; asm("mov.b64 %0, {%1, %2};" : "=l"(r) : "f"(x), "f"(y)); return r;
}
__device__ __forceinline__ float2 unpack2(u64 u) {
    float2 f; asm("mov.b64 {%0, %1}, %2;" : "=f"(f.x), "=f"(f.y) : "l"(u)); return f;
}
__device__ __forceinline__ float gelu_exact(float x) {
    return 0.5f * x * (1.0f + erff(x * 0.70710678118654752440f));
}
__device__ __forceinline__ float tf32r(float x) {
    float r; asm("cvt.rna.tf32.f32 %0, %1;" : "=f"(r) : "f"(x)); return r;
}
__device__ __forceinline__ void mma_tf32(float d[4], const unsigned a[4], unsigned b0, unsigned b1) {
    asm("mma.sync.aligned.m16n8k8.row.col.f32.tf32.tf32.f32 "
        "{%0,%1,%2,%3},{%4,%5,%6,%7},{%8,%9},{%0,%1,%2,%3};"
        : "+f"(d[0]), "+f"(d[1]), "+f"(d[2]), "+f"(d[3])
        : "r"(a[0]), "r"(a[1]), "r"(a[2]), "r"(a[3]), "r"(b0), "r"(b1));
}

// ---------------------------------------------------------------------------
// avgpool 2x2: x [B,C,128,128] -> xp tokens [B*N, C]
// ---------------------------------------------------------------------------
__global__ void avgpool_kernel(const float* __restrict__ x, float* __restrict__ xp) {
    int b  = blockIdx.x >> 6;
    int hp = blockIdx.x & 63;
    const float* xb = x + (size_t)b * CH * 128 * 128;
    float* xpb = xp + ((size_t)b * NTOK + (size_t)hp * 64) * CH;
    for (int idx = threadIdx.x; idx < 64 * CH; idx += blockDim.x) {
        int c  = idx & 63;
        int wp = idx >> 6;
        const float* p = xb + ((size_t)c * 128 + 2 * hp) * 128 + 2 * wp;
        xpb[(size_t)wp * CH + c] = 0.25f * (p[0] + p[1] + p[128] + p[129]);
    }
}

__global__ void gap_kernel(const float* __restrict__ x, float* __restrict__ gap) {
    int bc = blockIdx.x;
    const float* p = x + (size_t)bc * 16384;
    float s = 0.f;
    for (int i = threadIdx.x; i < 16384; i += 256) s += p[i];
    __shared__ float red[256];
    red[threadIdx.x] = s;
    __syncthreads();
    for (int st = 128; st > 0; st >>= 1) {
        if (threadIdx.x < st) red[threadIdx.x] += red[threadIdx.x + st];
        __syncthreads();
    }
    if (threadIdx.x == 0) gap[bc] = red[0] * (1.0f / 16384.0f);
}

// ---------------------------------------------------------------------------
// Fused q/k/v/xV (unchanged from R5)
// ---------------------------------------------------------------------------
__global__ void qkvo_kernel(const float* __restrict__ xp, const float* __restrict__ gap,
                            const float* __restrict__ Wq, const float* __restrict__ bq,
                            const float* __restrict__ Wk, const float* __restrict__ bk,
                            const float* __restrict__ Wv, const float* __restrict__ bv,
                            const float* __restrict__ Wo, const float* __restrict__ bo,
                            float* __restrict__ q, float* __restrict__ k,
                            float* __restrict__ v, float* __restrict__ xV) {
    extern __shared__ __align__(16) float sm[];
    float* Wt = sm;               // 4 * 4352
    float* xs = sm + 4 * 4352;    // 4352  plain
    float* xg = xs + 4352;        // 4352  gated
    float* gs = xg + 4352;        // 64
    int tid = threadIdx.x;
    int t0 = blockIdx.x * 64;
    int b  = t0 >> 12;
    const float* Ws[4] = {Wq, Wk, Wv, Wo};
    if (tid < 64) gs[tid] = gap[b * 64 + tid];
#pragma unroll
    for (int m = 0; m < 4; m++) {
        const float* W = Ws[m];
        for (int idx = tid; idx < 4096; idx += 256) {
            int o = idx >> 6, ci = idx & 63;
            Wt[m * 4352 + ci * 68 + o] = W[idx];
        }
    }
    __syncthreads();
    for (int idx = tid; idx < 4096; idx += 256) {
        int tt = idx >> 6, ci = idx & 63;
        float xv = xp[(size_t)(t0 + tt) * 64 + ci];
        xs[tt * 68 + ci] = xv;
        xg[tt * 68 + ci] = xv * gs[ci];
    }
    __syncthreads();
    int t = tid >> 2, qd = tid & 3;
    const float* biases[4] = {bq, bk, bv, bo};
    float* outs[4] = {q, k, v, xV};
#pragma unroll
    for (int m = 0; m < 4; m++) {
        const float* xrow = ((m < 3) ? xg : xs) + t * 68;
        const float* bb = biases[m];
        u64 acc[8];
#pragma unroll
        for (int o2 = 0; o2 < 8; o2++)
            acc[o2] = pack2(bb[qd * 16 + 2 * o2], bb[qd * 16 + 2 * o2 + 1]);
        const float* Wm = Wt + m * 4352;
#pragma unroll 8
        for (int ci = 0; ci < 64; ci++) {
            u64 xx = pack2(xrow[ci], xrow[ci]);
            const ulonglong2* wr = reinterpret_cast<const ulonglong2*>(Wm + ci * 68 + qd * 16);
#pragma unroll
            for (int w = 0; w < 4; w++) {
                ulonglong2 wv = wr[w];
                ffma2(acc[w * 2 + 0], xx, wv.x);
                ffma2(acc[w * 2 + 1], xx, wv.y);
            }
        }
        float4* op = reinterpret_cast<float4*>(outs[m] + (size_t)(t0 + t) * 64 + qd * 16);
#pragma unroll
        for (int w = 0; w < 4; w++) {
            float2 a = unpack2(acc[w * 2]);
            float2 c = unpack2(acc[w * 2 + 1]);
            op[w] = make_float4(a.x, a.y, c.x, c.y);
        }
    }
}

// ---------------------------------------------------------------------------
// Generic 64x64 linear (+optional residual, +optional fused LayerNorm).
// ---------------------------------------------------------------------------
__global__ void linear2_kernel(const float* __restrict__ in0, const float* __restrict__ W,
                               const float* __restrict__ bias, const float* __restrict__ res,
                               const float* __restrict__ lng, const float* __restrict__ lnb,
                               float* __restrict__ out) {
    __shared__ __align__(16) float Wt[4352];
    __shared__ __align__(16) float xs[4352];
    int tid = threadIdx.x;
    int t0 = blockIdx.x * 64;
    for (int idx = tid; idx < 4096; idx += 256) {
        int o = idx >> 6, ci = idx & 63;
        Wt[ci * 68 + o] = W[idx];
    }
    for (int idx = tid; idx < 4096; idx += 256) {
        int tt = idx >> 6, ci = idx & 63;
        xs[tt * 68 + ci] = in0[(size_t)(t0 + tt) * 64 + ci];
    }
    __syncthreads();
    int t = tid >> 2, qd = tid & 3;
    const float* xrow = xs + t * 68;
    u64 acc[8];
#pragma unroll
    for (int o2 = 0; o2 < 8; o2++)
        acc[o2] = pack2(bias[qd * 16 + 2 * o2], bias[qd * 16 + 2 * o2 + 1]);
#pragma unroll 8
    for (int ci = 0; ci < 64; ci++) {
        u64 xx = pack2(xrow[ci], xrow[ci]);
        const ulonglong2* wr = reinterpret_cast<const ulonglong2*>(Wt + ci * 68 + qd * 16);
#pragma unroll
        for (int w = 0; w < 4; w++) {
            ulonglong2 wv = wr[w];
            ffma2(acc[w * 2 + 0], xx, wv.x);
            ffma2(acc[w * 2 + 1], xx, wv.y);
        }
    }
    if (res) {
        const ulonglong2* rr = reinterpret_cast<const ulonglong2*>(res + (size_t)(t0 + t) * 64 + qd * 16);
#pragma unroll
        for (int w = 0; w < 4; w++) {
            ulonglong2 rv = rr[w];
            acc[w * 2 + 0] = fadd2(acc[w * 2 + 0], rv.x);
            acc[w * 2 + 1] = fadd2(acc[w * 2 + 1], rv.y);
        }
    }
    float val[16];
#pragma unroll
    for (int o2 = 0; o2 < 8; o2++) {
        float2 f = unpack2(acc[o2]);
        val[2 * o2] = f.x; val[2 * o2 + 1] = f.y;
    }
    if (lng) {
        float s = 0.f;
#pragma unroll
        for (int i = 0; i < 16; i++) s += val[i];
        s += __shfl_xor_sync(0xffffffffu, s, 1);
        s += __shfl_xor_sync(0xffffffffu, s, 2);
        float mu = s * (1.0f / 64.0f);
        float ss = 0.f;
#pragma unroll
        for (int i = 0; i < 16; i++) { float d = val[i] - mu; ss += d * d; }
        ss += __shfl_xor_sync(0xffffffffu, ss, 1);
        ss += __shfl_xor_sync(0xffffffffu, ss, 2);
        float rstd = rsqrtf(ss * (1.0f / 64.0f) + 1e-5f);
#pragma unroll
        for (int i = 0; i < 16; i++)
            val[i] = (val[i] - mu) * rstd * lng[qd * 16 + i] + lnb[qd * 16 + i];
    }
    float4* op = reinterpret_cast<float4*>(out + (size_t)(t0 + t) * 64 + qd * 16);
#pragma unroll
    for (int w = 0; w < 4; w++)
        op[w] = make_float4(val[4 * w], val[4 * w + 1], val[4 * w + 2], val[4 * w + 3]);
}

// ---------------------------------------------------------------------------
// Precompute composed strip weights (unchanged)
// ---------------------------------------------------------------------------
__global__ void comb_kernel(const float* __restrict__ convh_w, const float* __restrict__ convh_b,
                            const float* __restrict__ sch_pw, const float* __restrict__ sch_pwb,
                            const float* __restrict__ scv_pw, const float* __restrict__ scv_pwb,
                            float* __restrict__ combT_h, float* __restrict__ combT_v,
                            float* __restrict__ bias_comb) {
    extern __shared__ float s[];
    float* A = s; float* B1 = s + 4096; float* B2 = s + 8192;
    int tid = threadIdx.x;
    for (int idx = tid; idx < 4096; idx += 256) {
        A[idx] = convh_w[idx]; B1[idx] = sch_pw[idx]; B2[idx] = scv_pw[idx];
    }
    __syncthreads();
    for (int e = tid; e < 4096; e += 256) {
        int o = e >> 6, j = e & 63;
        float sh = 0.f, sv = 0.f;
        for (int i = 0; i < 64; i++) {
            float a = A[o * 64 + i];
            sh += a * B1[i * 64 + j];
            sv += a * B2[i * 64 + j];
        }
        combT_h[j * 64 + o] = sh;
        combT_v[j * 64 + o] = sv;
    }
    if (tid < 64) {
        float sb = 0.f;
        for (int i = 0; i < 64; i++) sb += A[tid * 64 + i] * (sch_pwb[i] + scv_pwb[i]);
        bias_comb[tid] = convh_b[tid] + sb;
    }
}

// ---------------------------------------------------------------------------
// Fused strip branch (unchanged)
// ---------------------------------------------------------------------------
__global__ void strip_kernel(const float* __restrict__ xp,
                             const float* __restrict__ sch_dw, const float* __restrict__ sch_dwb,
                             const float* __restrict__ scv_dw, const float* __restrict__ scv_dwb,
                             const float* __restrict__ combT_h, const float* __restrict__ combT_v,
                             const float* __restrict__ bias_comb, float* __restrict__ out) {
    extern __shared__ __align__(16) float sm[];
    float* WtH = sm;            // 4352
    float* WtV = sm + 4352;
    float* gh  = sm + 8704;
    float* gv  = sm + 13056;
    int tid = threadIdx.x;
    int t0 = blockIdx.x * 64;
    for (int idx = tid; idx < 4096; idx += 256) {
        int j = idx >> 6, o = idx & 63;
        WtH[j * 68 + o] = combT_h[idx];
        WtV[j * 68 + o] = combT_v[idx];
    }
    for (int idx = tid; idx < 4096; idx += 256) {
        int tt = idx >> 6, ci = idx & 63;
        int token = t0 + tt;
        int h = (token >> 6) & 63, w = token & 63;
        size_t base = (size_t)token * 64 + ci;
        float ah = sch_dwb[ci], av = scv_dwb[ci];
#pragma unroll
        for (int d = -2; d <= 2; d++) {
            int hh = h + d;
            if (hh >= 0 && hh < 64) ah += sch_dw[ci * 5 + d + 2] * xp[base + (ptrdiff_t)d * 4096];
            int ww = w + d;
            if (ww >= 0 && ww < 64) av += scv_dw[ci * 5 + d + 2] * xp[base + (ptrdiff_t)d * 64];
        }
        gh[tt * 68 + ci] = gelu_exact(ah);
        gv[tt * 68 + ci] = gelu_exact(av);
    }
    __syncthreads();
    int t = tid >> 2, qd = tid & 3;
    const float* hrow = gh + t * 68;
    const float* vrow = gv + t * 68;
    u64 acc[8];
#pragma unroll
    for (int o2 = 0; o2 < 8; o2++)
        acc[o2] = pack2(bias_comb[qd * 16 + 2 * o2], bias_comb[qd * 16 + 2 * o2 + 1]);
#pragma unroll 4
    for (int ci = 0; ci < 64; ci++) {
        u64 hx = pack2(hrow[ci], hrow[ci]);
        u64 vx = pack2(vrow[ci], vrow[ci]);
        const ulonglong2* wh = reinterpret_cast<const ulonglong2*>(WtH + ci * 68 + qd * 16);
        const ulonglong2* wv = reinterpret_cast<const ulonglong2*>(WtV + ci * 68 + qd * 16);
#pragma unroll
        for (int w = 0; w < 4; w++) {
            ulonglong2 wh2 = wh[w];
            ulonglong2 wv2 = wv[w];
            ffma2(acc[w * 2 + 0], hx, wh2.x);
            ffma2(acc[w * 2 + 1], hx, wh2.y);
            ffma2(acc[w * 2 + 0], vx, wv2.x);
            ffma2(acc[w * 2 + 1], vx, wv2.y);
        }
    }
    float4* op = reinterpret_cast<float4*>(out + (size_t)(t0 + t) * 64 + qd * 16);
#pragma unroll
    for (int w = 0; w < 4; w++) {
        float2 a = unpack2(acc[w * 2]);
        float2 c = unpack2(acc[w * 2 + 1]);
        op[w] = make_float4(a.x, a.y, c.x, c.y);
    }
}

// ---------------------------------------------------------------------------
// Depthwise 3x3 conv + bias + exact GELU (unchanged)
// ---------------------------------------------------------------------------
__global__ void dwconv3x3_kernel(const float* __restrict__ in,
                                 const float* __restrict__ wt,
                                 const float* __restrict__ bias,
                                 float* __restrict__ out) {
    int idx = blockIdx.x * 256 + threadIdx.x;
    int c = idx & 63;
    int g = idx >> 6;
    int n = g & 4095;
    int b = g >> 12;
    int h = n >> 6, w = n & 63;
    float acc = bias[c];
#pragma unroll
    for (int ky = 0; ky < 3; ky++) {
#pragma unroll
        for (int kx = 0; kx < 3; kx++) {
            int hh = h + ky - 1, ww = w + kx - 1;
            if (hh >= 0 && hh < 64 && ww >= 0 && ww < 64) {
                size_t src = (((size_t)b << 12) | ((size_t)hh << 6) | (size_t)ww) * 64 + c;
                acc += wt[c * 9 + ky * 3 + kx] * in[src];
            }
        }
    }
    out[(size_t)g * 64 + c] = gelu_exact(acc);
}

// ---------------------------------------------------------------------------
// Tensor-core flash attention (tf32 mma.sync.m16n8k8), fp32 accumulate.
// grid (32, B), 256 threads / 8 warps. Q tile = 128 rows; warp owns 16 rows.
// smem (dyn, 102400 B):
//   Qs  [128][68]  tf32(Q*scale)                              8704 fl
//   KsP [8ks][64n][4m][2]  pair {K[n][8ks+m], K[n][8ks+m+4]}  4096 fl
//   VsP [8js][64n][4m][2]  pair {V[8js+m][n], V[8js+m+4][n]}  4096 fl
//   Ps  [8 warps][16][68]  tf32(P)                            8704 fl
// Fragment reads are all conflict-free (pitch 68 / pair-packed LDS.64).
// ---------------------------------------------------------------------------
__global__ void attn_tc_kernel(const float* __restrict__ Q, const float* __restrict__ K,
                               const float* __restrict__ V, float* __restrict__ O) {
    extern __shared__ __align__(16) float sm[];
    float* Qs  = sm;              // 8704
    float* KsP = sm + 8704;       // 4096
    float* VsP = KsP + 4096;      // 4096
    float* Ps  = VsP + 4096;      // 8704

    int b  = blockIdx.y;
    int qt = blockIdx.x;
    const float* Qb = Q + ((size_t)b * NTOK + (size_t)qt * 128) * 64;
    const float* Kb = K + (size_t)b * NTOK * 64;
    const float* Vb = V + (size_t)b * NTOK * 64;
    float* Ob = O + ((size_t)b * NTOK + (size_t)qt * 128) * 64;

    int tid  = threadIdx.x;
    int warp = tid >> 5, lane = tid & 31;
    int gr = lane >> 2, mm = lane & 3;      // groupID, threadID-in-group
    float* Psw = Ps + warp * 1088;          // 16 x 68

    // stage Q (scaled, tf32)
    for (int idx = tid; idx < 8192; idx += 256) {
        int i = idx >> 6, c = idx & 63;
        Qs[i * 68 + c] = tf32r(Qb[idx] * ATT_SCALE);
    }
    __syncthreads();

    // Q A-fragments in registers for the whole loop
    unsigned qa[8][4];
    int qrow = warp * 16 + gr;
#pragma unroll
    for (int ks = 0; ks < 8; ks++) {
        qa[ks][0] = __float_as_uint(Qs[qrow * 68 + 8 * ks + mm]);
        qa[ks][1] = __float_as_uint(Qs[(qrow + 8) * 68 + 8 * ks + mm]);
        qa[ks][2] = __float_as_uint(Qs[qrow * 68 + 8 * ks + mm + 4]);
        qa[ks][3] = __float_as_uint(Qs[(qrow + 8) * 68 + 8 * ks + mm + 4]);
    }

    float mx0 = -1e30f, mx1 = -1e30f, l0 = 0.f, l1 = 0.f;
    float o[8][4];
#pragma unroll
    for (int nt = 0; nt < 8; nt++)
#pragma unroll
        for (int e = 0; e < 4; e++) o[nt][e] = 0.f;

    for (int kt = 0; kt < 64; kt++) {
        __syncthreads();
        const float* Kt = Kb + (size_t)kt * 4096;
        const float* Vt = Vb + (size_t)kt * 4096;
        for (int idx = tid; idx < 4096; idx += 256) {
            int j = idx >> 6, c = idx & 63;
            float kv = tf32r(Kt[idx]);
            float vv = tf32r(Vt[idx]);
            KsP[(c >> 3) * 512 + j * 8 + (c & 3) * 2 + ((c >> 2) & 1)] = kv;
            VsP[(j >> 3) * 512 + c * 8 + (j & 3) * 2 + ((j >> 2) & 1)] = vv;
        }
        __syncthreads();

        // S = Q K^T  (fp32 accum)
        float s[8][4];
#pragma unroll
        for (int nt = 0; nt < 8; nt++)
#pragma unroll
            for (int e = 0; e < 4; e++) s[nt][e] = 0.f;
#pragma unroll
        for (int ks = 0; ks < 8; ks++) {
#pragma unroll
            for (int nt = 0; nt < 8; nt++) {
                float2 bb = *reinterpret_cast<const float2*>(
                    &KsP[ks * 512 + (8 * nt + gr) * 8 + mm * 2]);
                mma_tf32(s[nt], qa[ks], __float_as_uint(bb.x), __float_as_uint(bb.y));
            }
        }

        // online softmax for rows qrow (vals s[nt][0..1]) and qrow+8 (s[nt][2..3])
        float rm0 = -1e30f, rm1 = -1e30f;
#pragma unroll
        for (int nt = 0; nt < 8; nt++) {
            rm0 = fmaxf(rm0, fmaxf(s[nt][0], s[nt][1]));
            rm1 = fmaxf(rm1, fmaxf(s[nt][2], s[nt][3]));
        }
        rm0 = fmaxf(rm0, __shfl_xor_sync(0xffffffffu, rm0, 1));
        rm0 = fmaxf(rm0, __shfl_xor_sync(0xffffffffu, rm0, 2));
        rm1 = fmaxf(rm1, __shfl_xor_sync(0xffffffffu, rm1, 1));
        rm1 = fmaxf(rm1, __shfl_xor_sync(0xffffffffu, rm1, 2));
        float mn0 = fmaxf(mx0, rm0), mn1 = fmaxf(mx1, rm1);
        float sf0 = __expf(mx0 - mn0), sf1 = __expf(mx1 - mn1);
        float rs0 = 0.f, rs1 = 0.f;
#pragma unroll
        for (int nt = 0; nt < 8; nt++) {
            s[nt][0] = __expf(s[nt][0] - mn0);
            s[nt][1] = __expf(s[nt][1] - mn0);
            s[nt][2] = __expf(s[nt][2] - mn1);
            s[nt][3] = __expf(s[nt][3] - mn1);
            rs0 += s[nt][0] + s[nt][1];
            rs1 += s[nt][2] + s[nt][3];
        }
        rs0 += __shfl_xor_sync(0xffffffffu, rs0, 1);
        rs0 += __shfl_xor_sync(0xffffffffu, rs0, 2);
        rs1 += __shfl_xor_sync(0xffffffffu, rs1, 1);
        rs1 += __shfl_xor_sync(0xffffffffu, rs1, 2);
        l0 = l0 * sf0 + rs0; mx0 = mn0;
        l1 = l1 * sf1 + rs1; mx1 = mn1;
#pragma unroll
        for (int nt = 0; nt < 8; nt++) {
            o[nt][0] *= sf0; o[nt][1] *= sf0;
            o[nt][2] *= sf1; o[nt][3] *= sf1;
        }
        // store P (tf32) to per-warp smem pad
#pragma unroll
        for (int nt = 0; nt < 8; nt++) {
            *reinterpret_cast<float2*>(&Psw[gr * 68 + 8 * nt + 2 * mm]) =
                make_float2(tf32r(s[nt][0]), tf32r(s[nt][1]));
            *reinterpret_cast<float2*>(&Psw[(gr + 8) * 68 + 8 * nt + 2 * mm]) =
                make_float2(tf32r(s[nt][2]), tf32r(s[nt][3]));
        }
        __syncwarp();

        // O += P V
#pragma unroll
        for (int js = 0; js < 8; js++) {
            unsigned pa[4];
            pa[0] = __float_as_uint(Psw[gr * 68 + 8 * js + mm]);
            pa[1] = __float_as_uint(Psw[(gr + 8) * 68 + 8 * js + mm]);
            pa[2] = __float_as_uint(Psw[gr * 68 + 8 * js + mm + 4]);
            pa[3] = __float_as_uint(Psw[(gr + 8) * 68 + 8 * js + mm + 4]);
#pragma unroll
            for (int nt = 0; nt < 8; nt++) {
                float2 bb = *reinterpret_cast<const float2*>(
                    &VsP[js * 512 + (8 * nt + gr) * 8 + mm * 2]);
                mma_tf32(o[nt], pa, __float_as_uint(bb.x), __float_as_uint(bb.y));
            }
        }
        __syncwarp();
    }

    float inv0 = 1.0f / l0, inv1 = 1.0f / l1;
#pragma unroll
    for (int nt = 0; nt < 8; nt++) {
        *reinterpret_cast<float2*>(&Ob[(size_t)qrow * 64 + 8 * nt + 2 * mm]) =
            make_float2(o[nt][0] * inv0, o[nt][1] * inv0);
        *reinterpret_cast<float2*>(&Ob[(size_t)(qrow + 8) * 64 + 8 * nt + 2 * mm]) =
            make_float2(o[nt][2] * inv1, o[nt][3] * inv1);
    }
}

// ---------------------------------------------------------------------------
// Bilinear x2 upsample (unchanged)
// ---------------------------------------------------------------------------
__global__ void upsample_kernel(const float* __restrict__ in, float* __restrict__ out) {
    int tid = threadIdx.x;
    int c = tid & 63;
    int p = blockIdx.x * 4 + (tid >> 6);
    int b = p >> 14;
    int rem = p & 16383;
    int y = rem >> 7, x = rem & 127;
    float sy = (float)y * (63.0f / 127.0f);
    int y0 = (int)sy; float wy = sy - (float)y0; int y1 = min(y0 + 1, 63);
    float sx = (float)x * (63.0f / 127.0f);
    int x0 = (int)sx; float wx = sx - (float)x0; int x1 = min(x0 + 1, 63);
    const float* base = in + (size_t)b * NTOK * 64;
    float v00 = base[((size_t)y0 * 64 + x0) * 64 + c];
    float v01 = base[((size_t)y0 * 64 + x1) * 64 + c];
    float v10 = base[((size_t)y1 * 64 + x0) * 64 + c];
    float v11 = base[((size_t)y1 * 64 + x1) * 64 + c];
    float r0 = v00 * (1.0f - wx) + v01 * wx;
    float r1 = v10 * (1.0f - wx) + v11 * wx;
    out[(((size_t)b * 64 + c) * 128 + y) * 128 + x] = r0 * (1.0f - wy) + r1 * wy;
}

// ---------------------------------------------------------------------------
extern "C" void kernel_launch(void* const* d_in, const int* in_sizes, int n_in,
                              void* d_out, int out_size) {
    const float* x       = (const float*)d_in[0];
    const float* Wq      = (const float*)d_in[1];
    const float* bq      = (const float*)d_in[2];
    const float* Wk      = (const float*)d_in[3];
    const float* bk      = (const float*)d_in[4];
    const float* Wv      = (const float*)d_in[5];
    const float* bv      = (const float*)d_in[6];
    const float* Wl      = (const float*)d_in[7];
    const float* bl      = (const float*)d_in[8];
    const float* Wo      = (const float*)d_in[9];
    const float* bo      = (const float*)d_in[10];
    const float* Wp      = (const float*)d_in[11];
    const float* bp      = (const float*)d_in[12];
    const float* sch_dw  = (const float*)d_in[13];
    const float* sch_dwb = (const float*)d_in[14];
    const float* sch_pw  = (const float*)d_in[15];
    const float* sch_pwb = (const float*)d_in[16];
    const float* scv_dw  = (const float*)d_in[17];
    const float* scv_dwb = (const float*)d_in[18];
    const float* scv_pw  = (const float*)d_in[19];
    const float* scv_pwb = (const float*)d_in[20];
    const float* convh_w = (const float*)d_in[21];
    const float* convh_b = (const float*)d_in[22];
    const float* dsc_dw  = (const float*)d_in[23];
    const float* dsc_dwb = (const float*)d_in[24];
    const float* dsc_pw  = (const float*)d_in[25];
    const float* dsc_pwb = (const float*)d_in[26];
    const float* ln_g    = (const float*)d_in[27];
    const float* ln_b    = (const float*)d_in[28];
    float* outp = (float*)d_out;

    float* S = nullptr; float* gap = nullptr;
    cudaGetSymbolAddress((void**)&S, g_scratch);
    cudaGetSymbolAddress((void**)&gap, g_gap);

    float* xp    = S + 0  * BUF_FLOATS;
    float* q     = S + 1  * BUF_FLOATS;
    float* k     = S + 2  * BUF_FLOATS;
    float* v     = S + 3  * BUF_FLOATS;
    float* xV    = S + 4  * BUF_FLOATS;
    float* attn1 = S + 5  * BUF_FLOATS;
    float* pl    = S + 6  * BUF_FLOATS;
    float* ph    = S + 7  * BUF_FLOATS;
    float* attn2 = S + 8  * BUF_FLOATS;
    float* pn    = S + 9  * BUF_FLOATS;
    float* tA    = S + 10 * BUF_FLOATS;
    float* dsco  = S + 11 * BUF_FLOATS;
    float* combT_h   = S + 12 * BUF_FLOATS;
    float* combT_v   = combT_h + 4096;
    float* bias_comb = combT_h + 8192;

    static int attr_done = 0;
    if (!attr_done) {
        cudaFuncSetAttribute(attn_tc_kernel, cudaFuncAttributeMaxDynamicSharedMemorySize, 102400);
        cudaFuncSetAttribute(qkvo_kernel, cudaFuncAttributeMaxDynamicSharedMemorySize, 104768);
        cudaFuncSetAttribute(strip_kernel, cudaFuncAttributeMaxDynamicSharedMemorySize, 69632);
        cudaFuncSetAttribute(comb_kernel, cudaFuncAttributeMaxDynamicSharedMemorySize, 49152);
        attr_done = 1;
    }

    // pooled tokens + GAP + composed strip weights
    avgpool_kernel<<<BATCH * 64, 256>>>(x, xp);
    gap_kernel<<<BATCH * CH, 256>>>(x, gap);
    comb_kernel<<<1, 256, 49152>>>(convh_w, convh_b, sch_pw, sch_pwb, scv_pw, scv_pwb,
                                   combT_h, combT_v, bias_comb);

    // q/k/v (gated) + xV (plain)
    qkvo_kernel<<<256, 256, 104768>>>(xp, gap, Wq, bq, Wk, bk, Wv, bv, Wo, bo, q, k, v, xV);

    // self-attention -> prompt_l
    attn_tc_kernel<<<dim3(32, BATCH), 256, 102400>>>(q, k, v, attn1);
    linear2_kernel<<<256, 256>>>(attn1, Wl, bl, nullptr, nullptr, nullptr, pl);

    // high-frequency branch (fused)
    strip_kernel<<<256, 256, 69632>>>(xp, sch_dw, sch_dwb, scv_dw, scv_dwb,
                                      combT_h, combT_v, bias_comb, ph);

    // cross-attention -> prompt, +xV residual, LayerNorm (fused epilogue)
    attn_tc_kernel<<<dim3(32, BATCH), 256, 102400>>>(ph, pl, xV, attn2);
    linear2_kernel<<<256, 256>>>(attn2, Wp, bp, xV, ln_g, ln_b, pn);

    // dsc: dw3x3 -> GELU -> pw + residual
    dwconv3x3_kernel<<<TOKALL * CH / 256, 256>>>(pn, dsc_dw, dsc_dwb, tA);
    linear2_kernel<<<256, 256>>>(tA, dsc_pw, dsc_pwb, pn, nullptr, nullptr, dsco);

    // bilinear x2 upsample
    upsample_kernel<<<BATCH * 128 * 128 / 4, 256>>>(dsco, outp);

    (void)in_sizes; (void)n_in; (void)out_size;
}

// round 10
// speedup vs baseline: 2.7159x; 1.4404x over previous
#include <cuda_runtime.h>
#include <math.h>
#include <stdint.h>

#define BATCH   4
#define CH      64
#define NTOK    4096
#define TOKALL  16384
#define ATT_SCALE 0.125f
#define QSCALE  (0.125f * 1.4426950408889634f)   // scale * log2(e)
#define BUF_FLOATS 1048576

__device__ float g_scratch[14 * BUF_FLOATS];
__device__ float g_gap[BATCH * CH];

__device__ __forceinline__ float gelu_exact(float x) {
    return 0.5f * x * (1.0f + erff(x * 0.70710678118654752440f));
}
__device__ __forceinline__ float tf32r(float x) {
    float r; asm("cvt.rna.tf32.f32 %0, %1;" : "=f"(r) : "f"(x)); return r;
}
__device__ __forceinline__ float ex2(float x) {
    float r; asm("ex2.approx.f32 %0, %1;" : "=f"(r) : "f"(x)); return r;
}
__device__ __forceinline__ void mma_tf32(float d[4], const unsigned a[4], unsigned b0, unsigned b1) {
    asm("mma.sync.aligned.m16n8k8.row.col.f32.tf32.tf32.f32 "
        "{%0,%1,%2,%3},{%4,%5,%6,%7},{%8,%9},{%0,%1,%2,%3};"
        : "+f"(d[0]), "+f"(d[1]), "+f"(d[2]), "+f"(d[3])
        : "r"(a[0]), "r"(a[1]), "r"(a[2]), "r"(a[3]), "r"(b0), "r"(b1));
}

// ---- shared TC-linear building blocks -------------------------------------
// A-fragments for rows r0, r0+8 from X[.][68] tile (tf32 pre-converted).
__device__ __forceinline__ void load_afrag(unsigned a[8][4], const float* X, int r0, int mm) {
#pragma unroll
    for (int ks = 0; ks < 8; ks++) {
        a[ks][0] = __float_as_uint(X[r0 * 68 + 8 * ks + mm]);
        a[ks][1] = __float_as_uint(X[(r0 + 8) * 68 + 8 * ks + mm]);
        a[ks][2] = __float_as_uint(X[r0 * 68 + 8 * ks + mm + 4]);
        a[ks][3] = __float_as_uint(X[(r0 + 8) * 68 + 8 * ks + mm + 4]);
    }
}
__device__ __forceinline__ void init_acc(float acc[8][4], const float* bs, int mm) {
#pragma unroll
    for (int nt = 0; nt < 8; nt++) {
        float b0 = bs[8 * nt + 2 * mm], b1 = bs[8 * nt + 2 * mm + 1];
        acc[nt][0] = b0; acc[nt][1] = b1; acc[nt][2] = b0; acc[nt][3] = b1;
    }
}
__device__ __forceinline__ void mm_core(float acc[8][4], const unsigned a[8][4],
                                        const float* WsP, int gr, int mm) {
#pragma unroll
    for (int ks = 0; ks < 8; ks++)
#pragma unroll
        for (int nt = 0; nt < 8; nt++) {
            float2 bb = *reinterpret_cast<const float2*>(&WsP[ks * 512 + (8 * nt + gr) * 8 + mm * 2]);
            mma_tf32(acc[nt], a[ks], __float_as_uint(bb.x), __float_as_uint(bb.y));
        }
}
__device__ __forceinline__ void store_acc(const float acc[8][4], float* out,
                                          int t0, int r0, int mm) {
#pragma unroll
    for (int nt = 0; nt < 8; nt++) {
        *reinterpret_cast<float2*>(&out[(size_t)(t0 + r0) * 64 + 8 * nt + 2 * mm]) =
            make_float2(acc[nt][0], acc[nt][1]);
        *reinterpret_cast<float2*>(&out[(size_t)(t0 + r0 + 8) * 64 + 8 * nt + 2 * mm]) =
            make_float2(acc[nt][2], acc[nt][3]);
    }
}
// W pair-packing position for element (o, ci): {W[o][8ks+mm], W[o][8ks+mm+4]}
__device__ __forceinline__ int wpos(int o, int ci) {
    return (ci >> 3) * 512 + o * 8 + (ci & 3) * 2 + ((ci >> 2) & 1);
}

// ---------------------------------------------------------------------------
// avgpool 2x2: x [B,C,128,128] -> xp tokens [B*N, C]
// ---------------------------------------------------------------------------
__global__ void avgpool_kernel(const float* __restrict__ x, float* __restrict__ xp) {
    int b  = blockIdx.x >> 6;
    int hp = blockIdx.x & 63;
    const float* xb = x + (size_t)b * CH * 128 * 128;
    float* xpb = xp + ((size_t)b * NTOK + (size_t)hp * 64) * CH;
    for (int idx = threadIdx.x; idx < 64 * CH; idx += blockDim.x) {
        int c  = idx & 63;
        int wp = idx >> 6;
        const float* p = xb + ((size_t)c * 128 + 2 * hp) * 128 + 2 * wp;
        xpb[(size_t)wp * CH + c] = 0.25f * (p[0] + p[1] + p[128] + p[129]);
    }
}

__global__ void gap_kernel(const float* __restrict__ x, float* __restrict__ gap) {
    int bc = blockIdx.x;
    const float* p = x + (size_t)bc * 16384;
    float s = 0.f;
    for (int i = threadIdx.x; i < 16384; i += 256) s += p[i];
    __shared__ float red[256];
    red[threadIdx.x] = s;
    __syncthreads();
    for (int st = 128; st > 0; st >>= 1) {
        if (threadIdx.x < st) red[threadIdx.x] += red[threadIdx.x + st];
        __syncthreads();
    }
    if (threadIdx.x == 0) gap[bc] = red[0] * (1.0f / 16384.0f);
}

// ---------------------------------------------------------------------------
// Composed strip weights: comb_h[o][j] = sum_i convh[o,i]*sch_pw[i,j] (row-major)
// ---------------------------------------------------------------------------
__global__ void comb_kernel(const float* __restrict__ convh_w, const float* __restrict__ convh_b,
                            const float* __restrict__ sch_pw, const float* __restrict__ sch_pwb,
                            const float* __restrict__ scv_pw, const float* __restrict__ scv_pwb,
                            float* __restrict__ comb_h, float* __restrict__ comb_v,
                            float* __restrict__ bias_comb) {
    extern __shared__ float s[];
    float* A = s; float* B1 = s + 4096; float* B2 = s + 8192;
    int tid = threadIdx.x;
    for (int idx = tid; idx < 4096; idx += 256) {
        A[idx] = convh_w[idx]; B1[idx] = sch_pw[idx]; B2[idx] = scv_pw[idx];
    }
    __syncthreads();
    for (int e = tid; e < 4096; e += 256) {
        int o = e >> 6, j = e & 63;
        float sh = 0.f, sv = 0.f;
        for (int i = 0; i < 64; i++) {
            float a = A[o * 64 + i];
            sh += a * B1[i * 64 + j];
            sv += a * B2[i * 64 + j];
        }
        comb_h[o * 64 + j] = sh;
        comb_v[o * 64 + j] = sv;
    }
    if (tid < 64) {
        float sb = 0.f;
        for (int i = 0; i < 64; i++) sb += A[tid * 64 + i] * (sch_pwb[i] + scv_pwb[i]);
        bias_comb[tid] = convh_b[tid] + sb;
    }
}

// ---------------------------------------------------------------------------
// TC qkvo: q,k,v from gated tokens, xV from plain. grid 128, 256 thr.
// smem 34048 floats.
// ---------------------------------------------------------------------------
__global__ void qkvo_tc_kernel(const float* __restrict__ xp, const float* __restrict__ gap,
                               const float* __restrict__ Wq, const float* __restrict__ bq,
                               const float* __restrict__ Wk, const float* __restrict__ bk,
                               const float* __restrict__ Wv, const float* __restrict__ bv,
                               const float* __restrict__ Wo, const float* __restrict__ bo,
                               float* __restrict__ q, float* __restrict__ k,
                               float* __restrict__ v, float* __restrict__ xV) {
    extern __shared__ __align__(16) float sm[];
    float* Xg  = sm;            // 8704
    float* Xs  = sm + 8704;     // 8704
    float* Wp4 = sm + 17408;    // 16384
    float* bs  = sm + 33792;    // 256
    int tid = threadIdx.x;
    int t0 = blockIdx.x * 128;
    int b = t0 >> 12;
    for (int idx = tid; idx < 8192; idx += 256) {
        int t = idx >> 6, c = idx & 63;
        float xv = xp[(size_t)(t0 + t) * 64 + c];
        Xs[t * 68 + c] = tf32r(xv);
        Xg[t * 68 + c] = tf32r(xv * __ldg(&gap[b * 64 + c]));
    }
    for (int idx = tid; idx < 4096; idx += 256) {
        int o = idx >> 6, ci = idx & 63;
        int pos = wpos(o, ci);
        Wp4[pos]         = tf32r(Wq[idx]);
        Wp4[4096 + pos]  = tf32r(Wk[idx]);
        Wp4[8192 + pos]  = tf32r(Wv[idx]);
        Wp4[12288 + pos] = tf32r(Wo[idx]);
    }
    if (tid < 64) {
        bs[tid] = bq[tid]; bs[64 + tid] = bk[tid];
        bs[128 + tid] = bv[tid]; bs[192 + tid] = bo[tid];
    }
    __syncthreads();
    int warp = tid >> 5, lane = tid & 31, gr = lane >> 2, mm = lane & 3;
    int r0 = warp * 16 + gr;
    unsigned a[8][4];
    float acc[8][4];
    load_afrag(a, Xg, r0, mm);
    init_acc(acc, bs, mm);       mm_core(acc, a, Wp4, gr, mm);         store_acc(acc, q, t0, r0, mm);
    init_acc(acc, bs + 64, mm);  mm_core(acc, a, Wp4 + 4096, gr, mm);  store_acc(acc, k, t0, r0, mm);
    init_acc(acc, bs + 128, mm); mm_core(acc, a, Wp4 + 8192, gr, mm);  store_acc(acc, v, t0, r0, mm);
    load_afrag(a, Xs, r0, mm);
    init_acc(acc, bs + 192, mm); mm_core(acc, a, Wp4 + 12288, gr, mm); store_acc(acc, xV, t0, r0, mm);
}

// ---------------------------------------------------------------------------
// TC 64x64 linear (+optional residual, +optional LN). grid 128, 256 thr.
// smem 12992 floats.
// ---------------------------------------------------------------------------
__global__ void linear_tc_kernel(const float* __restrict__ in0, const float* __restrict__ W,
                                 const float* __restrict__ bias, const float* __restrict__ res,
                                 const float* __restrict__ lng, const float* __restrict__ lnb,
                                 float* __restrict__ out) {
    extern __shared__ __align__(16) float sm[];
    float* Xs  = sm;           // 8704
    float* WsP = sm + 8704;    // 4096
    float* bs  = sm + 12800;   // 64
    float* lg  = sm + 12864;   // 64
    float* lb  = sm + 12928;   // 64
    int tid = threadIdx.x;
    int t0 = blockIdx.x * 128;
    for (int idx = tid; idx < 8192; idx += 256) {
        int t = idx >> 6, c = idx & 63;
        Xs[t * 68 + c] = tf32r(in0[(size_t)(t0 + t) * 64 + c]);
    }
    for (int idx = tid; idx < 4096; idx += 256) {
        int o = idx >> 6, ci = idx & 63;
        WsP[wpos(o, ci)] = tf32r(W[idx]);
    }
    if (tid < 64) {
        bs[tid] = bias[tid];
        if (lng) { lg[tid] = lng[tid]; lb[tid] = lnb[tid]; }
    }
    __syncthreads();
    int warp = tid >> 5, lane = tid & 31, gr = lane >> 2, mm = lane & 3;
    int r0 = warp * 16 + gr;
    unsigned a[8][4];
    load_afrag(a, Xs, r0, mm);
    float acc[8][4];
    init_acc(acc, bs, mm);
    mm_core(acc, a, WsP, gr, mm);
    if (res) {
#pragma unroll
        for (int nt = 0; nt < 8; nt++) {
            float2 r0v = *reinterpret_cast<const float2*>(&res[(size_t)(t0 + r0) * 64 + 8 * nt + 2 * mm]);
            float2 r1v = *reinterpret_cast<const float2*>(&res[(size_t)(t0 + r0 + 8) * 64 + 8 * nt + 2 * mm]);
            acc[nt][0] += r0v.x; acc[nt][1] += r0v.y;
            acc[nt][2] += r1v.x; acc[nt][3] += r1v.y;
        }
    }
    if (lng) {
        float s0 = 0.f, s1 = 0.f;
#pragma unroll
        for (int nt = 0; nt < 8; nt++) { s0 += acc[nt][0] + acc[nt][1]; s1 += acc[nt][2] + acc[nt][3]; }
        s0 += __shfl_xor_sync(0xffffffffu, s0, 1); s0 += __shfl_xor_sync(0xffffffffu, s0, 2);
        s1 += __shfl_xor_sync(0xffffffffu, s1, 1); s1 += __shfl_xor_sync(0xffffffffu, s1, 2);
        float mu0 = s0 * (1.0f / 64.0f), mu1 = s1 * (1.0f / 64.0f);
        float q0 = 0.f, q1 = 0.f;
#pragma unroll
        for (int nt = 0; nt < 8; nt++) {
            float d0 = acc[nt][0] - mu0, d1 = acc[nt][1] - mu0;
            float d2 = acc[nt][2] - mu1, d3 = acc[nt][3] - mu1;
            q0 += d0 * d0 + d1 * d1; q1 += d2 * d2 + d3 * d3;
        }
        q0 += __shfl_xor_sync(0xffffffffu, q0, 1); q0 += __shfl_xor_sync(0xffffffffu, q0, 2);
        q1 += __shfl_xor_sync(0xffffffffu, q1, 1); q1 += __shfl_xor_sync(0xffffffffu, q1, 2);
        float rstd0 = rsqrtf(q0 * (1.0f / 64.0f) + 1e-5f);
        float rstd1 = rsqrtf(q1 * (1.0f / 64.0f) + 1e-5f);
#pragma unroll
        for (int nt = 0; nt < 8; nt++) {
            int c0 = 8 * nt + 2 * mm;
            acc[nt][0] = (acc[nt][0] - mu0) * rstd0 * lg[c0] + lb[c0];
            acc[nt][1] = (acc[nt][1] - mu0) * rstd0 * lg[c0 + 1] + lb[c0 + 1];
            acc[nt][2] = (acc[nt][2] - mu1) * rstd1 * lg[c0] + lb[c0];
            acc[nt][3] = (acc[nt][3] - mu1) * rstd1 * lg[c0 + 1] + lb[c0 + 1];
        }
    }
    store_acc(acc, out, t0, r0, mm);
}

// ---------------------------------------------------------------------------
// TC strip branch: dw5+gelu staged, dual composed matmul accumulated. grid 128.
// smem 25664 floats.
// ---------------------------------------------------------------------------
__global__ void strip_tc_kernel(const float* __restrict__ xp,
                                const float* __restrict__ sch_dw, const float* __restrict__ sch_dwb,
                                const float* __restrict__ scv_dw, const float* __restrict__ scv_dwb,
                                const float* __restrict__ comb_h, const float* __restrict__ comb_v,
                                const float* __restrict__ bias_comb, float* __restrict__ out) {
    extern __shared__ __align__(16) float sm[];
    float* Gh   = sm;           // 8704
    float* Gv   = sm + 8704;    // 8704
    float* WsPH = sm + 17408;   // 4096
    float* WsPV = sm + 21504;   // 4096
    float* bs   = sm + 25600;   // 64
    int tid = threadIdx.x;
    int t0 = blockIdx.x * 128;
    for (int idx = tid; idx < 8192; idx += 256) {
        int tt = idx >> 6, ci = idx & 63;
        int token = t0 + tt;
        int h = (token >> 6) & 63, w = token & 63;
        size_t base = (size_t)token * 64 + ci;
        float ah = sch_dwb[ci], av = scv_dwb[ci];
#pragma unroll
        for (int d = -2; d <= 2; d++) {
            int hh = h + d;
            if (hh >= 0 && hh < 64) ah += sch_dw[ci * 5 + d + 2] * xp[base + (ptrdiff_t)d * 4096];
            int ww = w + d;
            if (ww >= 0 && ww < 64) av += scv_dw[ci * 5 + d + 2] * xp[base + (ptrdiff_t)d * 64];
        }
        Gh[tt * 68 + ci] = tf32r(gelu_exact(ah));
        Gv[tt * 68 + ci] = tf32r(gelu_exact(av));
    }
    for (int idx = tid; idx < 4096; idx += 256) {
        int o = idx >> 6, ci = idx & 63;
        int pos = wpos(o, ci);
        WsPH[pos] = tf32r(comb_h[idx]);
        WsPV[pos] = tf32r(comb_v[idx]);
    }
    if (tid < 64) bs[tid] = bias_comb[tid];
    __syncthreads();
    int warp = tid >> 5, lane = tid & 31, gr = lane >> 2, mm = lane & 3;
    int r0 = warp * 16 + gr;
    unsigned a[8][4];
    float acc[8][4];
    init_acc(acc, bs, mm);
    load_afrag(a, Gh, r0, mm); mm_core(acc, a, WsPH, gr, mm);
    load_afrag(a, Gv, r0, mm); mm_core(acc, a, WsPV, gr, mm);
    store_acc(acc, out, t0, r0, mm);
}

// ---------------------------------------------------------------------------
// TC dsc: stage gelu(dw3x3(pn)), matmul dsc_pw, +pn residual. grid 128.
// smem 12864 floats.
// ---------------------------------------------------------------------------
__global__ void dsc_tc_kernel(const float* __restrict__ pn,
                              const float* __restrict__ dsc_dw, const float* __restrict__ dsc_dwb,
                              const float* __restrict__ dsc_pw, const float* __restrict__ dsc_pwb,
                              float* __restrict__ out) {
    extern __shared__ __align__(16) float sm[];
    float* Xs  = sm;           // 8704
    float* WsP = sm + 8704;    // 4096
    float* bs  = sm + 12800;   // 64
    int tid = threadIdx.x;
    int t0 = blockIdx.x * 128;
    for (int idx = tid; idx < 8192; idx += 256) {
        int tt = idx >> 6, ci = idx & 63;
        int token = t0 + tt;
        int b = token >> 12;
        int h = (token >> 6) & 63, w = token & 63;
        float acc = dsc_dwb[ci];
#pragma unroll
        for (int ky = 0; ky < 3; ky++) {
#pragma unroll
            for (int kx = 0; kx < 3; kx++) {
                int hh = h + ky - 1, ww = w + kx - 1;
                if (hh >= 0 && hh < 64 && ww >= 0 && ww < 64) {
                    size_t src = (((size_t)b << 12) | ((size_t)hh << 6) | (size_t)ww) * 64 + ci;
                    acc += dsc_dw[ci * 9 + ky * 3 + kx] * pn[src];
                }
            }
        }
        Xs[tt * 68 + ci] = tf32r(gelu_exact(acc));
    }
    for (int idx = tid; idx < 4096; idx += 256) {
        int o = idx >> 6, ci = idx & 63;
        WsP[wpos(o, ci)] = tf32r(dsc_pw[idx]);
    }
    if (tid < 64) bs[tid] = dsc_pwb[tid];
    __syncthreads();
    int warp = tid >> 5, lane = tid & 31, gr = lane >> 2, mm = lane & 3;
    int r0 = warp * 16 + gr;
    unsigned a[8][4];
    load_afrag(a, Xs, r0, mm);
    float acc[8][4];
    init_acc(acc, bs, mm);
    mm_core(acc, a, WsP, gr, mm);
#pragma unroll
    for (int nt = 0; nt < 8; nt++) {
        float2 r0v = *reinterpret_cast<const float2*>(&pn[(size_t)(t0 + r0) * 64 + 8 * nt + 2 * mm]);
        float2 r1v = *reinterpret_cast<const float2*>(&pn[(size_t)(t0 + r0 + 8) * 64 + 8 * nt + 2 * mm]);
        acc[nt][0] += r0v.x; acc[nt][1] += r0v.y;
        acc[nt][2] += r1v.x; acc[nt][3] += r1v.y;
    }
    store_acc(acc, out, t0, r0, mm);
}

// ---------------------------------------------------------------------------
// Tensor-core flash attention (tf32), no-max softmax (scores provably small),
// scale*log2e folded into Q, ex2.approx, l reduced once at the end.
// grid (32, B), 256 threads / 8 warps. smem 102400 B.
// ---------------------------------------------------------------------------
__global__ void attn_tc_kernel(const float* __restrict__ Q, const float* __restrict__ K,
                               const float* __restrict__ V, float* __restrict__ O) {
    extern __shared__ __align__(16) float sm[];
    float* Qs  = sm;              // 8704
    float* KsP = sm + 8704;       // 4096
    float* VsP = KsP + 4096;      // 4096
    float* Ps  = VsP + 4096;      // 8704

    int b  = blockIdx.y;
    int qt = blockIdx.x;
    const float* Qb = Q + ((size_t)b * NTOK + (size_t)qt * 128) * 64;
    const float* Kb = K + (size_t)b * NTOK * 64;
    const float* Vb = V + (size_t)b * NTOK * 64;
    float* Ob = O + ((size_t)b * NTOK + (size_t)qt * 128) * 64;

    int tid  = threadIdx.x;
    int warp = tid >> 5, lane = tid & 31;
    int gr = lane >> 2, mm = lane & 3;
    float* Psw = Ps + warp * 1088;

    for (int idx = tid; idx < 8192; idx += 256) {
        int i = idx >> 6, c = idx & 63;
        Qs[i * 68 + c] = tf32r(Qb[idx] * QSCALE);
    }
    __syncthreads();

    unsigned qa[8][4];
    int qrow = warp * 16 + gr;
    load_afrag(qa, Qs, qrow, mm);

    float l0 = 0.f, l1 = 0.f;
    float o[8][4];
#pragma unroll
    for (int nt = 0; nt < 8; nt++)
#pragma unroll
        for (int e = 0; e < 4; e++) o[nt][e] = 0.f;

    for (int kt = 0; kt < 64; kt++) {
        __syncthreads();
        const float* Kt = Kb + (size_t)kt * 4096;
        const float* Vt = Vb + (size_t)kt * 4096;
        for (int idx = tid; idx < 4096; idx += 256) {
            int j = idx >> 6, c = idx & 63;
            KsP[(c >> 3) * 512 + j * 8 + (c & 3) * 2 + ((c >> 2) & 1)] = tf32r(Kt[idx]);
            VsP[(j >> 3) * 512 + c * 8 + (j & 3) * 2 + ((j >> 2) & 1)] = tf32r(Vt[idx]);
        }
        __syncthreads();

        // S' = Q K^T (already in log2 domain)
        float s[8][4];
#pragma unroll
        for (int nt = 0; nt < 8; nt++)
#pragma unroll
            for (int e = 0; e < 4; e++) s[nt][e] = 0.f;
#pragma unroll
        for (int ks = 0; ks < 8; ks++) {
#pragma unroll
            for (int nt = 0; nt < 8; nt++) {
                float2 bb = *reinterpret_cast<const float2*>(
                    &KsP[ks * 512 + (8 * nt + gr) * 8 + mm * 2]);
                mma_tf32(s[nt], qa[ks], __float_as_uint(bb.x), __float_as_uint(bb.y));
            }
        }

        // exp (no max subtraction), accumulate l, store P
        float rs0 = 0.f, rs1 = 0.f;
#pragma unroll
        for (int nt = 0; nt < 8; nt++) {
            float e0 = ex2(s[nt][0]), e1 = ex2(s[nt][1]);
            float e2 = ex2(s[nt][2]), e3 = ex2(s[nt][3]);
            rs0 += e0 + e1; rs1 += e2 + e3;
            *reinterpret_cast<float2*>(&Psw[gr * 68 + 8 * nt + 2 * mm]) =
                make_float2(tf32r(e0), tf32r(e1));
            *reinterpret_cast<float2*>(&Psw[(gr + 8) * 68 + 8 * nt + 2 * mm]) =
                make_float2(tf32r(e2), tf32r(e3));
        }
        l0 += rs0; l1 += rs1;
        __syncwarp();

        // O += P V
#pragma unroll
        for (int js = 0; js < 8; js++) {
            unsigned pa[4];
            pa[0] = __float_as_uint(Psw[gr * 68 + 8 * js + mm]);
            pa[1] = __float_as_uint(Psw[(gr + 8) * 68 + 8 * js + mm]);
            pa[2] = __float_as_uint(Psw[gr * 68 + 8 * js + mm + 4]);
            pa[3] = __float_as_uint(Psw[(gr + 8) * 68 + 8 * js + mm + 4]);
#pragma unroll
            for (int nt = 0; nt < 8; nt++) {
                float2 bb = *reinterpret_cast<const float2*>(
                    &VsP[js * 512 + (8 * nt + gr) * 8 + mm * 2]);
                mma_tf32(o[nt], pa, __float_as_uint(bb.x), __float_as_uint(bb.y));
            }
        }
        __syncwarp();
    }

    // row sums of l across the mm quad, then normalize
    l0 += __shfl_xor_sync(0xffffffffu, l0, 1); l0 += __shfl_xor_sync(0xffffffffu, l0, 2);
    l1 += __shfl_xor_sync(0xffffffffu, l1, 1); l1 += __shfl_xor_sync(0xffffffffu, l1, 2);
    float inv0 = 1.0f / l0, inv1 = 1.0f / l1;
#pragma unroll
    for (int nt = 0; nt < 8; nt++) {
        *reinterpret_cast<float2*>(&Ob[(size_t)qrow * 64 + 8 * nt + 2 * mm]) =
            make_float2(o[nt][0] * inv0, o[nt][1] * inv0);
        *reinterpret_cast<float2*>(&Ob[(size_t)(qrow + 8) * 64 + 8 * nt + 2 * mm]) =
            make_float2(o[nt][2] * inv1, o[nt][3] * inv1);
    }
}

// ---------------------------------------------------------------------------
// Bilinear x2 upsample (unchanged)
// ---------------------------------------------------------------------------
__global__ void upsample_kernel(const float* __restrict__ in, float* __restrict__ out) {
    int tid = threadIdx.x;
    int c = tid & 63;
    int p = blockIdx.x * 4 + (tid >> 6);
    int b = p >> 14;
    int rem = p & 16383;
    int y = rem >> 7, x = rem & 127;
    float sy = (float)y * (63.0f / 127.0f);
    int y0 = (int)sy; float wy = sy - (float)y0; int y1 = min(y0 + 1, 63);
    float sx = (float)x * (63.0f / 127.0f);
    int x0 = (int)sx; float wx = sx - (float)x0; int x1 = min(x0 + 1, 63);
    const float* base = in + (size_t)b * NTOK * 64;
    float v00 = base[((size_t)y0 * 64 + x0) * 64 + c];
    float v01 = base[((size_t)y0 * 64 + x1) * 64 + c];
    float v10 = base[((size_t)y1 * 64 + x0) * 64 + c];
    float v11 = base[((size_t)y1 * 64 + x1) * 64 + c];
    float r0 = v00 * (1.0f - wx) + v01 * wx;
    float r1 = v10 * (1.0f - wx) + v11 * wx;
    out[(((size_t)b * 64 + c) * 128 + y) * 128 + x] = r0 * (1.0f - wy) + r1 * wy;
}

// ---------------------------------------------------------------------------
extern "C" void kernel_launch(void* const* d_in, const int* in_sizes, int n_in,
                              void* d_out, int out_size) {
    const float* x       = (const float*)d_in[0];
    const float* Wq      = (const float*)d_in[1];
    const float* bq      = (const float*)d_in[2];
    const float* Wk      = (const float*)d_in[3];
    const float* bk      = (const float*)d_in[4];
    const float* Wv      = (const float*)d_in[5];
    const float* bv      = (const float*)d_in[6];
    const float* Wl      = (const float*)d_in[7];
    const float* bl      = (const float*)d_in[8];
    const float* Wo      = (const float*)d_in[9];
    const float* bo      = (const float*)d_in[10];
    const float* Wp      = (const float*)d_in[11];
    const float* bp      = (const float*)d_in[12];
    const float* sch_dw  = (const float*)d_in[13];
    const float* sch_dwb = (const float*)d_in[14];
    const float* sch_pw  = (const float*)d_in[15];
    const float* sch_pwb = (const float*)d_in[16];
    const float* scv_dw  = (const float*)d_in[17];
    const float* scv_dwb = (const float*)d_in[18];
    const float* scv_pw  = (const float*)d_in[19];
    const float* scv_pwb = (const float*)d_in[20];
    const float* convh_w = (const float*)d_in[21];
    const float* convh_b = (const float*)d_in[22];
    const float* dsc_dw  = (const float*)d_in[23];
    const float* dsc_dwb = (const float*)d_in[24];
    const float* dsc_pw  = (const float*)d_in[25];
    const float* dsc_pwb = (const float*)d_in[26];
    const float* ln_g    = (const float*)d_in[27];
    const float* ln_b    = (const float*)d_in[28];
    float* outp = (float*)d_out;

    float* S = nullptr; float* gap = nullptr;
    cudaGetSymbolAddress((void**)&S, g_scratch);
    cudaGetSymbolAddress((void**)&gap, g_gap);

    float* xp    = S + 0  * BUF_FLOATS;
    float* q     = S + 1  * BUF_FLOATS;
    float* k     = S + 2  * BUF_FLOATS;
    float* v     = S + 3  * BUF_FLOATS;
    float* xV    = S + 4  * BUF_FLOATS;
    float* attn1 = S + 5  * BUF_FLOATS;
    float* pl    = S + 6  * BUF_FLOATS;
    float* ph    = S + 7  * BUF_FLOATS;
    float* attn2 = S + 8  * BUF_FLOATS;
    float* pn    = S + 9  * BUF_FLOATS;
    float* dsco  = S + 10 * BUF_FLOATS;
    float* comb_h    = S + 11 * BUF_FLOATS;
    float* comb_v    = comb_h + 4096;
    float* bias_comb = comb_h + 8192;

    cudaFuncSetAttribute(attn_tc_kernel, cudaFuncAttributeMaxDynamicSharedMemorySize, 102400);
    cudaFuncSetAttribute(qkvo_tc_kernel, cudaFuncAttributeMaxDynamicSharedMemorySize, 136192);
    cudaFuncSetAttribute(linear_tc_kernel, cudaFuncAttributeMaxDynamicSharedMemorySize, 51968);
    cudaFuncSetAttribute(strip_tc_kernel, cudaFuncAttributeMaxDynamicSharedMemorySize, 102656);
    cudaFuncSetAttribute(dsc_tc_kernel, cudaFuncAttributeMaxDynamicSharedMemorySize, 51456);
    cudaFuncSetAttribute(comb_kernel, cudaFuncAttributeMaxDynamicSharedMemorySize, 49152);

    // pooled tokens + GAP + composed strip weights
    avgpool_kernel<<<BATCH * 64, 256>>>(x, xp);
    gap_kernel<<<BATCH * CH, 256>>>(x, gap);
    comb_kernel<<<1, 256, 49152>>>(convh_w, convh_b, sch_pw, sch_pwb, scv_pw, scv_pwb,
                                   comb_h, comb_v, bias_comb);

    // q/k/v (gated) + xV (plain)
    qkvo_tc_kernel<<<128, 256, 136192>>>(xp, gap, Wq, bq, Wk, bk, Wv, bv, Wo, bo, q, k, v, xV);

    // self-attention -> prompt_l
    attn_tc_kernel<<<dim3(32, BATCH), 256, 102400>>>(q, k, v, attn1);
    linear_tc_kernel<<<128, 256, 51968>>>(attn1, Wl, bl, nullptr, nullptr, nullptr, pl);

    // high-frequency branch (fused)
    strip_tc_kernel<<<128, 256, 102656>>>(xp, sch_dw, sch_dwb, scv_dw, scv_dwb,
                                          comb_h, comb_v, bias_comb, ph);

    // cross-attention -> prompt, +xV residual, LayerNorm (fused)
    attn_tc_kernel<<<dim3(32, BATCH), 256, 102400>>>(ph, pl, xV, attn2);
    linear_tc_kernel<<<128, 256, 51968>>>(attn2, Wp, bp, xV, ln_g, ln_b, pn);

    // dsc: dw3x3+gelu staged, pw matmul + residual (fused)
    dsc_tc_kernel<<<128, 256, 51456>>>(pn, dsc_dw, dsc_dwb, dsc_pw, dsc_pwb, dsco);

    // bilinear x2 upsample
    upsample_kernel<<<BATCH * 128 * 128 / 4, 256>>>(dsco, outp);

    (void)in_sizes; (void)n_in; (void)out_size;
}